// round 1
// baseline (speedup 1.0000x reference)
#include <cuda_runtime.h>
#include <math.h>

#define D_    196
#define NCH_  64
#define H_    8
#define DH_   64
#define INNER_ 512
#define MLP_  784
#define SEQ_  65

// ---- scratch (no allocations allowed) ----
__device__ float g_a[NCH_ * D_];          // post conv+bn+relu rows
__device__ float g_xatt[SEQ_ * D_];       // gated rows + tokens row
__device__ float g_qkv[SEQ_ * 3 * INNER_];// [n][q(512) k(512) v(512)] (q pre-scaled)
__device__ float g_o[SEQ_ * INNER_];      // attention output, [n][h*64+d]
__device__ float g_x2[SEQ_ * D_];         // after attn residual block
__device__ float g_t[SEQ_ * MLP_];        // gelu(ff1)

// ============================================================
// K1: conv+bn+relu, channel gating, x_att assembly. One block.
// ============================================================
__global__ __launch_bounds__(256) void k_gating(
    const float* __restrict__ x_pe, const float* __restrict__ tokens,
    const float* __restrict__ conv_k,
    const float* __restrict__ bn_g, const float* __restrict__ bn_b,
    const float* __restrict__ bn_rm, const float* __restrict__ bn_rv,
    const float* __restrict__ fc_w1, const float* __restrict__ fc_w2)
{
    __shared__ float b1s[NCH_];
    __shared__ float b2s[NCH_];
    __shared__ float hid[12];
    __shared__ float cs[NCH_];

    const int tid  = threadIdx.x;
    const int warp = tid >> 5, lane = tid & 31;

    const float k0 = conv_k[3], k1 = conv_k[4], k2 = conv_k[5]; // conv_k[1][:]
    const float rm = bn_rm[0];
    const float inv = rsqrtf(bn_rv[0] + 1e-5f) * bn_g[0];
    const float bb  = bn_b[0];

    // conv (1D, kernel row 1) + bn + relu, per channel; warp per channel
    for (int ch = warp; ch < NCH_; ch += 8) {
        const float* row = x_pe + ch * D_;
        float s = 0.f;
        for (int d = lane; d < D_; d += 32) {
            float xm = (d > 0)        ? row[d - 1] : 0.f;
            float xc = row[d];
            float xp = (d < D_ - 1)   ? row[d + 1] : 0.f;
            float conv = k0 * xm + k1 * xc + k2 * xp;
            float bn = (conv - rm) * inv + bb;
            float av = fmaxf(bn, 0.f);
            g_a[ch * D_ + d] = av;
            s += av;
        }
        #pragma unroll
        for (int o = 16; o; o >>= 1) s += __shfl_down_sync(0xffffffffu, s, o);
        if (lane == 0) b1s[ch] = s * (1.f / 196.f);
    }
    __syncthreads();

    // sort-based suppress/excite (rank via O(64^2) stable counting)
    if (tid < NCH_) {
        const float bi = b1s[tid];
        float mx = -1e30f, mn = 1e30f;
        int cnt_nonpos = 0, rank = 0;
        #pragma unroll 8
        for (int j = 0; j < NCH_; j++) {
            float bj = b1s[j];
            mx = fmaxf(mx, bj);
            mn = fminf(mn, bj);
            if (bj <= 0.f) cnt_nonpos++;
            if (bj < bi || (bj == bi && j < tid)) rank++;
        }
        int middle = (mx < 0.f || mn > 0.f) ? 32 : (mx > 0.f ? cnt_nonpos : 0);
        float b2;
        if (rank < middle) {
            float ls = (float)middle;
            b2 = bi - 1.f / (1.f + powf(ls, bi));
        } else {
            float le = (float)(NCH_ - middle);
            b2 = bi + 1.f / (1.f + powf(le, -bi));
        }
        b2s[tid] = b2;
    }
    __syncthreads();

    if (tid < 12) {
        float s = 0.f;
        #pragma unroll 8
        for (int i = 0; i < NCH_; i++) s += b2s[i] * fc_w1[i * 12 + tid];
        hid[tid] = fmaxf(s, 0.f);
    }
    __syncthreads();
    if (tid < NCH_) {
        float s = 0.f;
        #pragma unroll
        for (int j = 0; j < 12; j++) s += hid[j] * fc_w2[j * NCH_ + tid];
        cs[tid] = 1.f / (1.f + expf(-s));
    }
    __syncthreads();

    for (int idx = tid; idx < NCH_ * D_; idx += 256)
        g_xatt[idx] = g_a[idx] * cs[idx / D_];
    for (int d = tid; d < D_; d += 256)
        g_xatt[NCH_ * D_ + d] = tokens[d];
}

// ============================================================
// K2: LN1 (per-row, recomputed per block) fused into QKV GEMM.
// grid (6, 65), 256 threads. j = bx*256+tid in [0,1536).
// q slice pre-scaled by DH^-0.5.
// ============================================================
__global__ __launch_bounds__(256) void k_qkv(
    const float* __restrict__ x,
    const float* __restrict__ ln1_g, const float* __restrict__ ln1_b,
    const float* __restrict__ w_qkv)
{
    __shared__ float h[D_];
    __shared__ float w1[8], w2[8];
    __shared__ float mean_s, rstd_s;

    const int tid = threadIdx.x;
    const int n = blockIdx.y;
    const float* xr = x + n * D_;

    float v = (tid < D_) ? xr[tid] : 0.f;
    float s1 = v, s2 = v * v;
    #pragma unroll
    for (int o = 16; o; o >>= 1) {
        s1 += __shfl_down_sync(0xffffffffu, s1, o);
        s2 += __shfl_down_sync(0xffffffffu, s2, o);
    }
    if ((tid & 31) == 0) { w1[tid >> 5] = s1; w2[tid >> 5] = s2; }
    __syncthreads();
    if (tid == 0) {
        float t1 = 0.f, t2 = 0.f;
        #pragma unroll
        for (int i = 0; i < 8; i++) { t1 += w1[i]; t2 += w2[i]; }
        float mean = t1 * (1.f / 196.f);
        float var  = t2 * (1.f / 196.f) - mean * mean;
        mean_s = mean;
        rstd_s = rsqrtf(var + 1e-5f);
    }
    __syncthreads();
    if (tid < D_) h[tid] = (v - mean_s) * rstd_s * ln1_g[tid] + ln1_b[tid];
    __syncthreads();

    const int j = blockIdx.x * 256 + tid;       // < 1536 always
    const float* w = w_qkv + j;
    float acc = 0.f;
    #pragma unroll 4
    for (int k = 0; k < D_; k++) acc += h[k] * w[k * (3 * INNER_)];
    if (j < INNER_) acc *= 0.125f;               // DH^-0.5
    g_qkv[n * (3 * INNER_) + j] = acc;
}

// ============================================================
// K3: attention. grid (65, 8): (n, head). 128 threads.
// ============================================================
__global__ __launch_bounds__(128) void k_attn()
{
    const int n = blockIdx.x, hh = blockIdx.y;
    const int tid = threadIdx.x;
    __shared__ float q[DH_];
    __shared__ float sc[SEQ_];
    __shared__ float smax, sinv;

    if (tid < DH_) q[tid] = g_qkv[n * (3 * INNER_) + hh * DH_ + tid];
    __syncthreads();

    if (tid < SEQ_) {
        const float* kr = g_qkv + tid * (3 * INNER_) + INNER_ + hh * DH_;
        float s = 0.f;
        #pragma unroll 8
        for (int d = 0; d < DH_; d++) s += q[d] * kr[d];
        sc[tid] = s;
    }
    __syncthreads();
    if (tid == 0) {
        float mx = sc[0];
        for (int i = 1; i < SEQ_; i++) mx = fmaxf(mx, sc[i]);
        smax = mx;
    }
    __syncthreads();
    if (tid < SEQ_) sc[tid] = expf(sc[tid] - smax);
    __syncthreads();
    if (tid == 0) {
        float sum = 0.f;
        for (int i = 0; i < SEQ_; i++) sum += sc[i];
        sinv = 1.f / sum;
    }
    __syncthreads();
    if (tid < DH_) {
        const float* vbase = g_qkv + 2 * INNER_ + hh * DH_ + tid;
        float acc = 0.f;
        for (int m = 0; m < SEQ_; m++) acc += sc[m] * vbase[m * (3 * INNER_)];
        g_o[n * INNER_ + hh * DH_ + tid] = acc * sinv;
    }
}

// ============================================================
// K4: out-proj + residuals. grid 65, 256 threads.
// ============================================================
__global__ __launch_bounds__(256) void k_outproj(
    const float* __restrict__ x,
    const float* __restrict__ w_out, const float* __restrict__ b_out)
{
    __shared__ float o[INNER_];
    const int n = blockIdx.x, tid = threadIdx.x;
    for (int i = tid; i < INNER_; i += 256) o[i] = g_o[n * INNER_ + i];
    __syncthreads();
    if (tid < D_) {
        float acc = b_out[tid] + x[n * D_ + tid] + g_xatt[n * D_ + tid];
        const float* w = w_out + tid;
        #pragma unroll 8
        for (int i = 0; i < INNER_; i++) acc += o[i] * w[i * D_];
        g_x2[n * D_ + tid] = acc;
    }
}

// ============================================================
// K5: LN2 fused into FF1 + exact GELU. grid (4, 65), 256 thr.
// ============================================================
__global__ __launch_bounds__(256) void k_ff1(
    const float* __restrict__ ln2_g, const float* __restrict__ ln2_b,
    const float* __restrict__ ff_w1, const float* __restrict__ ff_b1)
{
    __shared__ float h[D_];
    __shared__ float w1[8], w2[8];
    __shared__ float mean_s, rstd_s;

    const int tid = threadIdx.x;
    const int n = blockIdx.y;
    const float* xr = g_x2 + n * D_;

    float v = (tid < D_) ? xr[tid] : 0.f;
    float s1 = v, s2 = v * v;
    #pragma unroll
    for (int o = 16; o; o >>= 1) {
        s1 += __shfl_down_sync(0xffffffffu, s1, o);
        s2 += __shfl_down_sync(0xffffffffu, s2, o);
    }
    if ((tid & 31) == 0) { w1[tid >> 5] = s1; w2[tid >> 5] = s2; }
    __syncthreads();
    if (tid == 0) {
        float t1 = 0.f, t2 = 0.f;
        #pragma unroll
        for (int i = 0; i < 8; i++) { t1 += w1[i]; t2 += w2[i]; }
        float mean = t1 * (1.f / 196.f);
        float var  = t2 * (1.f / 196.f) - mean * mean;
        mean_s = mean;
        rstd_s = rsqrtf(var + 1e-5f);
    }
    __syncthreads();
    if (tid < D_) h[tid] = (v - mean_s) * rstd_s * ln2_g[tid] + ln2_b[tid];
    __syncthreads();

    const int j = blockIdx.x * 256 + tid;
    if (j < MLP_) {
        const float* w = ff_w1 + j;
        float acc = ff_b1[j];
        #pragma unroll 4
        for (int k = 0; k < D_; k++) acc += h[k] * w[k * MLP_];
        // exact gelu: 0.5*x*(1+erf(x/sqrt(2)))
        g_t[n * MLP_ + j] = 0.5f * acc * (1.f + erff(acc * 0.70710678118654752f));
    }
}

// ============================================================
// K6: FF2 + residual -> out. grid 65, 256 threads.
// ============================================================
__global__ __launch_bounds__(256) void k_ff2(
    const float* __restrict__ ff_w2, const float* __restrict__ ff_b2,
    float* __restrict__ out)
{
    __shared__ float t[MLP_];
    const int n = blockIdx.x, tid = threadIdx.x;
    for (int i = tid; i < MLP_; i += 256) t[i] = g_t[n * MLP_ + i];
    __syncthreads();
    if (tid < D_) {
        float acc = ff_b2[tid] + g_x2[n * D_ + tid];
        const float* w = ff_w2 + tid;
        #pragma unroll 8
        for (int k = 0; k < MLP_; k++) acc += t[k] * w[k * D_];
        out[n * D_ + tid] = acc;
    }
}

// ============================================================
extern "C" void kernel_launch(void* const* d_in, const int* in_sizes, int n_in,
                              void* d_out, int out_size)
{
    const float* x      = (const float*)d_in[0];
    const float* tokens = (const float*)d_in[1];
    const float* x_pe   = (const float*)d_in[2];
    const float* conv_k = (const float*)d_in[3];
    const float* bn_g   = (const float*)d_in[4];
    const float* bn_b   = (const float*)d_in[5];
    const float* bn_rm  = (const float*)d_in[6];
    const float* bn_rv  = (const float*)d_in[7];
    const float* fc_w1  = (const float*)d_in[8];
    const float* fc_w2  = (const float*)d_in[9];
    const float* ln1_g  = (const float*)d_in[10];
    const float* ln1_b  = (const float*)d_in[11];
    const float* ln2_g  = (const float*)d_in[12];
    const float* ln2_b  = (const float*)d_in[13];
    const float* w_qkv  = (const float*)d_in[14];
    const float* w_out  = (const float*)d_in[15];
    const float* b_out  = (const float*)d_in[16];
    const float* ff_w1  = (const float*)d_in[17];
    const float* ff_b1  = (const float*)d_in[18];
    const float* ff_w2  = (const float*)d_in[19];
    const float* ff_b2  = (const float*)d_in[20];
    float* out = (float*)d_out;

    k_gating<<<1, 256>>>(x_pe, tokens, conv_k, bn_g, bn_b, bn_rm, bn_rv, fc_w1, fc_w2);
    k_qkv<<<dim3(6, SEQ_), 256>>>(x, ln1_g, ln1_b, w_qkv);
    k_attn<<<dim3(SEQ_, H_), 128>>>();
    k_outproj<<<SEQ_, 256>>>(x, w_out, b_out);
    k_ff1<<<dim3(4, SEQ_), 256>>>(ln2_g, ln2_b, ff_w1, ff_b1);
    k_ff2<<<SEQ_, 256>>>(ff_w2, ff_b2, out);
}